// round 1
// baseline (speedup 1.0000x reference)
#include <cuda_runtime.h>
#include <math.h>

// Problem constants
#define NSIG   32768          // B*H*W signals
#define KDICT  512            // N_EMBED
#define DIMF   64             // DIM
#define HWSZ   4096           // H*W
#define REGEPS 1e-7f
#define TOPK   327            // int(32768*0.01)

// Output packing (flattened tuple, float32)
#define OUT_N    2097152      // out [8,64,64,64]
#define DIFF_OFS 2097152      // diff_enc, diff_dict
#define IDS_OFS  2097154      // ids [8,512,64,64]
#define IDS_N    16777216
#define SCAL_OFS 18874370     // num_steps, mean_D, mean_Z, norm_Z, top_percentile, num_zeros

// Device scratch (static allocation — no cudaMalloc allowed)
__device__ float  g_Dn[DIMF * KDICT];        // normalized dict [d][j]
__device__ float  g_DnT[KDICT * DIMF];       // transposed [j][d]
__device__ float  g_G[KDICT * KDICT];        // Gram
__device__ float  g_alpha0[(size_t)NSIG * KDICT];  // 64MB
__device__ double g_meanD, g_absZ, g_diff;
__device__ int    g_hist[8];

__global__ void init_k() {
    g_meanD = 0.0; g_absZ = 0.0; g_diff = 0.0;
    for (int i = 0; i < 8; i++) g_hist[i] = 0;
}

// Normalize dictionary columns; accumulate sum|Dn| for mean_D.
__global__ void prep_k(const float* __restrict__ dict) {
    int j = threadIdx.x;   // 512 threads, one per atom
    float ss = 0.f;
#pragma unroll
    for (int d = 0; d < DIMF; d++) { float v = dict[d * KDICT + j]; ss += v * v; }
    float nrm = sqrtf(ss);
    double asum = 0.0;
#pragma unroll
    for (int d = 0; d < DIMF; d++) {
        float v = dict[d * KDICT + j] / nrm;
        g_Dn[d * KDICT + j] = v;
        g_DnT[j * DIMF + d] = v;
        asum += (double)fabsf(v);
    }
    atomicAdd(&g_meanD, asum);
}

// G = Dn^T Dn. 64 blocks x 512 threads; each block does 8 rows of G,
// thread j keeps its Dn column in registers (64 floats).
__global__ void gram_k() {
    int j = threadIdx.x;
    int i0 = blockIdx.x * 8;
    float r[DIMF];
#pragma unroll
    for (int d = 0; d < DIMF; d++) r[d] = g_Dn[d * KDICT + j];
    __shared__ float sc[8][DIMF];
    { int t = threadIdx.x; sc[t >> 6][t & 63] = g_DnT[i0 * DIMF + t]; }
    __syncthreads();
#pragma unroll
    for (int ii = 0; ii < 8; ii++) {
        float acc = 0.f;
#pragma unroll
        for (int d = 0; d < DIMF; d++) acc += r[d] * sc[ii][d];
        g_G[(i0 + ii) * KDICT + j] = acc;
    }
}

// alpha0 = Xperm @ Dn. Xperm signal n=(b,hw): x[b*262144 + d*4096 + hw].
// Tile: BM=128 signals, BN=64 atoms, K=64 (full). 256 threads, 8x4 micro.
__global__ __launch_bounds__(256) void gemm_k(const float* __restrict__ x) {
    __shared__ float Xs[DIMF][128];
    __shared__ float Ds[DIMF][64];
    int tid = threadIdx.x;
    int m0 = blockIdx.y * 128;           // 128 consecutive hw within one b
    int bb = m0 >> 12, hw0 = m0 & 4095;
    const float* xb = x + (size_t)bb * 262144 + hw0;
    for (int i = tid; i < DIMF * 128; i += 256) {
        int d = i >> 7, m = i & 127;
        Xs[d][m] = xb[(size_t)d * 4096 + m];
    }
    int n0 = blockIdx.x * 64;
    for (int i = tid; i < DIMF * 64; i += 256) {
        int d = i >> 6, nn = i & 63;
        Ds[d][nn] = g_Dn[d * KDICT + n0 + nn];
    }
    __syncthreads();
    int tx = tid & 15, ty = tid >> 4;
    float acc[8][4];
#pragma unroll
    for (int i = 0; i < 8; i++)
#pragma unroll
        for (int jj = 0; jj < 4; jj++) acc[i][jj] = 0.f;
#pragma unroll
    for (int d = 0; d < DIMF; d++) {
        float4 a0 = *(const float4*)&Xs[d][ty * 8];
        float4 a1 = *(const float4*)&Xs[d][ty * 8 + 4];
        float4 bv = *(const float4*)&Ds[d][tx * 4];
        float am[8] = {a0.x, a0.y, a0.z, a0.w, a1.x, a1.y, a1.z, a1.w};
        float bn[4] = {bv.x, bv.y, bv.z, bv.w};
#pragma unroll
        for (int mm = 0; mm < 8; mm++)
#pragma unroll
            for (int nn = 0; nn < 4; nn++) acc[mm][nn] += am[mm] * bn[nn];
    }
#pragma unroll
    for (int mm = 0; mm < 8; mm++) {
        int n = m0 + ty * 8 + mm;
        float4 v = make_float4(acc[mm][0], acc[mm][1], acc[mm][2], acc[mm][3]);
        *(float4*)&g_alpha0[(size_t)n * KDICT + n0 + tx * 4] = v;
    }
}

// Zero-fill ids region of output (poisoned buffer).
__global__ void zero_ids_k(float* __restrict__ out) {
    float2* p = (float2*)(out + IDS_OFS);   // 8-byte aligned
    size_t total = IDS_N / 2;
    for (size_t i = blockIdx.x * (size_t)blockDim.x + threadIdx.x; i < total;
         i += (size_t)gridDim.x * blockDim.x)
        p[i] = make_float2(0.f, 0.f);
}

// Main OMP kernel: one warp per signal, 8 signals/block.
// Dynamic smem: sGrow[8][4][512] (64KB) + sq[64][9] (2.25KB).
extern __shared__ float s_omp[];
__global__ __launch_bounds__(256) void omp_k(float* __restrict__ out) {
    float (*sGrow)[4][KDICT] = (float (*)[4][KDICT])s_omp;
    float (*sq)[9] = (float (*)[9])(s_omp + 8 * 4 * KDICT);
    int wid = threadIdx.x >> 5, lane = threadIdx.x & 31;
    int n = blockIdx.x * 8 + wid;
    int bb = n >> 12, hw = n & 4095;
    const float* a0p = g_alpha0 + (size_t)n * KDICT;

    float a0[16], al[16];
#pragma unroll
    for (int t = 0; t < 16; t++) { a0[t] = a0p[lane + 32 * t]; al[t] = a0[t]; }

    int idxs[4]; float gam[4]; float Gs[4][4]; float rh[4];

#pragma unroll
    for (int k = 0; k < 4; k++) {
        // argmax |alpha| with first-index tie-break (j = lane + 32*t)
        float bvv = -1.f; int bj = 0;
#pragma unroll
        for (int t = 0; t < 16; t++) {
            float v = fabsf(al[t]);
            if (v > bvv) { bvv = v; bj = lane + 32 * t; }
        }
#pragma unroll
        for (int off = 16; off >= 1; off >>= 1) {
            float ov = __shfl_down_sync(0xffffffffu, bvv, off);
            int   oj = __shfl_down_sync(0xffffffffu, bj, off);
            if (ov > bvv || (ov == bvv && oj < bj)) { bvv = ov; bj = oj; }
        }
        bj = __shfl_sync(0xffffffffu, bj, 0);
        idxs[k] = bj;

        // cache G row in shared (each lane writes/reads its own 16 slots)
        const float* grow = g_G + (size_t)bj * KDICT;
#pragma unroll
        for (int t = 0; t < 16; t++) sGrow[wid][k][lane + 32 * t] = grow[lane + 32 * t];

        // new Gram-submatrix entries + rhs (uniform loads, L2 hits)
#pragma unroll
        for (int a = 0; a < 4; a++) if (a <= k) {
            float v = grow[idxs[a]];
            Gs[k][a] = v; Gs[a][k] = v;
        }
        rh[k] = a0p[bj];

        // Solve (Gs + eps I) gamma = rh, size k+1, Gaussian elimination (SPD, diag~1)
        float M[4][4], y[4];
#pragma unroll
        for (int i = 0; i < 4; i++) if (i <= k) {
            y[i] = rh[i];
#pragma unroll
            for (int jj = 0; jj < 4; jj++) if (jj <= k)
                M[i][jj] = Gs[i][jj] + (i == jj ? REGEPS : 0.f);
        }
#pragma unroll
        for (int c = 0; c < 4; c++) {
            if (c > k) break;
            float inv = 1.f / M[c][c];
#pragma unroll
            for (int r2 = c + 1; r2 < 4; r2++) if (r2 <= k) {
                float f = M[r2][c] * inv;
#pragma unroll
                for (int cc = c + 1; cc < 4; cc++) M[r2][cc] -= f * M[c][cc];
                y[r2] -= f * y[c];
            }
        }
#pragma unroll
        for (int r2 = 3; r2 >= 0; r2--) if (r2 <= k) {
            float s = y[r2];
#pragma unroll
            for (int cc = r2 + 1; cc < 4; cc++) if (cc <= k) s -= M[r2][cc] * gam[cc];
            gam[r2] = s / M[r2][r2];
        }

        // recompute alpha = alpha0 - sum_a gamma_a * G[idx_a,:] (skip on last iter)
        if (k < 3) {
#pragma unroll
            for (int t = 0; t < 16; t++) {
                float s = a0[t];
#pragma unroll
                for (int a = 0; a < 4; a++) if (a <= k)
                    s -= gam[a] * sGrow[wid][a][lane + 32 * t];
                al[t] = s;
            }
        }
    }

    // quant[n][d] = sum_a gam[a] * DnT[idxs[a]][d] -> smem transpose
#pragma unroll
    for (int rep = 0; rep < 2; rep++) {
        int d = lane + rep * 32;
        float s = 0.f;
#pragma unroll
        for (int a = 0; a < 4; a++) s += gam[a] * g_DnT[idxs[a] * DIMF + d];
        sq[d][wid] = s;
    }

    if (lane == 0) {
        float* ids = out + IDS_OFS + (size_t)bb * (KDICT * HWSZ) + hw;
        ids[(size_t)idxs[0] * HWSZ] = gam[0];
        ids[(size_t)idxs[1] * HWSZ] = gam[1];
        ids[(size_t)idxs[2] * HWSZ] = gam[2];
        ids[(size_t)idxs[3] * HWSZ] = gam[3];
        double az = (double)fabsf(gam[0]) + (double)fabsf(gam[1]) +
                    (double)fabsf(gam[2]) + (double)fabsf(gam[3]);
        atomicAdd(&g_absZ, az);
        int c = (gam[0] != 0.f) + (gam[1] != 0.f) + (gam[2] != 0.f) + (gam[3] != 0.f);
        atomicAdd(&g_hist[c], 1);
    }
    __syncthreads();

    // write out[b][d][hw] (same layout as x) for this block's 8 signals
    int base_n = blockIdx.x * 8;
    int b0 = base_n >> 12, hw0 = base_n & 4095;
    for (int i = threadIdx.x; i < 512; i += 256) {
        int d = i >> 3, s2 = i & 7;
        out[(size_t)b0 * 262144 + (size_t)d * 4096 + hw0 + s2] = sq[d][s2];
    }
}

// diff_enc = mean((quant - x)^2) elementwise over identical layouts
__global__ void diff_k(const float* __restrict__ x, const float* __restrict__ out) {
    __shared__ double sd[256];
    double loc = 0.0;
    for (size_t i = blockIdx.x * (size_t)blockDim.x + threadIdx.x; i < OUT_N;
         i += (size_t)gridDim.x * blockDim.x) {
        float d = out[i] - x[i];
        loc += (double)d * (double)d;
    }
    sd[threadIdx.x] = loc;
    __syncthreads();
    for (int s = 128; s > 0; s >>= 1) {
        if (threadIdx.x < s) sd[threadIdx.x] += sd[threadIdx.x + s];
        __syncthreads();
    }
    if (threadIdx.x == 0) atomicAdd(&g_diff, sd[0]);
}

__global__ void fin_k(float* __restrict__ out) {
    float diff = (float)(g_diff / (double)OUT_N);
    out[DIFF_OFS]     = diff;
    out[DIFF_OFS + 1] = diff;
    out[SCAL_OFS + 0] = 4.0f;  // num_steps
    out[SCAL_OFS + 1] = (float)(g_meanD / (double)(DIMF * KDICT));
    out[SCAL_OFS + 2] = (float)(g_absZ / (double)((size_t)NSIG * KDICT));
    long long nnzsum = 0;
    for (int c = 0; c <= 4; c++) nnzsum += (long long)c * g_hist[c];
    out[SCAL_OFS + 3] = (float)((double)nnzsum / (double)NSIG);
    int cum = 0; float tp = 0.f;
    for (int v = 4; v >= 0; v--) { cum += g_hist[v]; if (cum >= TOPK) { tp = (float)v; break; } }
    out[SCAL_OFS + 4] = tp;
    out[SCAL_OFS + 5] = (float)g_hist[0];
}

extern "C" void kernel_launch(void* const* d_in, const int* in_sizes, int n_in,
                              void* d_out, int out_size) {
    const float* x = (const float*)d_in[0];
    const float* dict = (const float*)d_in[1];
    if (n_in >= 2 && in_sizes[0] == DIMF * KDICT && in_sizes[1] == OUT_N) {
        // defensive: inputs arrived swapped
        const float* t = x; x = dict; dict = t;
    }
    float* out = (float*)d_out;

    const int omp_smem = 8 * 4 * KDICT * 4 + 64 * 9 * 4;   // 67840 B
    cudaFuncSetAttribute(omp_k, cudaFuncAttributeMaxDynamicSharedMemorySize, omp_smem);

    init_k<<<1, 1>>>();
    prep_k<<<1, 512>>>(dict);
    gram_k<<<64, 512>>>();
    dim3 gg(KDICT / 64, NSIG / 128);
    gemm_k<<<gg, 256>>>(x);
    zero_ids_k<<<8192, 256>>>(out);
    omp_k<<<NSIG / 8, 256, omp_smem>>>(out);
    diff_k<<<2048, 256>>>(x, out);
    fin_k<<<1, 1>>>(out);
}